// round 1
// baseline (speedup 1.0000x reference)
#include <cuda_runtime.h>
#include <cuda_bf16.h>

// S4D forward as an exact diagonal-SSM recurrence (equivalent to the
// reference's Vandermonde-kernel + FFT convolution, in exact arithmetic):
//   a[d,n]  = exp(dt_d * A_n),  A_n = -0.5*(n+1)
//   cb[d,n] = C[d,n] * B[d,n] * expm1(dt_d*A_n) / A_n
//   h_n[l]  = a_n*h_n[l-1] + x[l]
//   y[l]    = sum_n cb_n * h_n[l] + D_d * x[l]
//
// Mapping: block = (batch b, 32-channel tile), lane = channel (coalesced x/y),
// warp = 8-state slice of N=64. 16 timesteps per barrier round; cross-warp
// reduction through shared memory.

#define BATCH   8
#define LEN     2048
#define DMODEL  1024
#define NSTATE  64

#define WARPS   8
#define SPT     8      // states per thread (NSTATE / WARPS)
#define CHT     32     // channel tile (lanes)
#define RST     16     // timesteps per reduction round

__global__ __launch_bounds__(WARPS * 32, 2)
void s4d_recurrence_kernel(const float* __restrict__ x,
                           const float* __restrict__ log_dt,
                           const float* __restrict__ Bm,
                           const float* __restrict__ Cm,
                           const float* __restrict__ Dv,
                           float* __restrict__ y)
{
    __shared__ float P[WARPS][RST][CHT];

    const int lane = threadIdx.x & 31;
    const int w    = threadIdx.x >> 5;
    const int d0   = blockIdx.x * CHT;
    const int b    = blockIdx.y;
    const int d    = d0 + lane;

    // ---- per-thread discretized parameters (8 states of channel d) ----
    float a[SPT], cb[SPT], s[SPT];
    const float dt = expf(log_dt[d]);
    #pragma unroll
    for (int i = 0; i < SPT; i++) {
        const int   n   = w * SPT + i;
        const float An  = -0.5f * (float)(n + 1);
        const float dtA = dt * An;
        a[i]  = expf(dtA);
        cb[i] = Cm[d * NSTATE + n] * Bm[d * NSTATE + n] * (expm1f(dtA) / An);
        s[i]  = 0.0f;
    }
    const float Dd = Dv[d];

    const float* xb = x + (size_t)b * LEN * DMODEL + d;   // x[b, :, d]
    float*       yb = y + (size_t)b * LEN * DMODEL + d;   // y[b, :, d]

    for (int l0 = 0; l0 < LEN; l0 += RST) {
        // ---- compute phase: 16 steps, per-thread partial contributions ----
        float p[RST];
        #pragma unroll
        for (int r = 0; r < RST; r++) {
            const float xv = xb[(size_t)(l0 + r) * DMODEL];
            #pragma unroll
            for (int i = 0; i < SPT; i++)
                s[i] = fmaf(a[i], s[i], xv);
            float acc = cb[0] * s[0];
            #pragma unroll
            for (int i = 1; i < SPT; i++)
                acc = fmaf(cb[i], s[i], acc);
            p[r] = acc;
        }

        // ---- cross-warp reduction through smem ----
        #pragma unroll
        for (int r = 0; r < RST; r++)
            P[w][r][lane] = p[r];
        __syncthreads();

        // warp w reduces rows r = w and r = w + 8 for all 32 channels
        #pragma unroll
        for (int k = 0; k < 2; k++) {
            const int r = w + k * WARPS;
            float sum = P[0][r][lane];
            #pragma unroll
            for (int ww = 1; ww < WARPS; ww++)
                sum += P[ww][r][lane];
            const float xv = xb[(size_t)(l0 + r) * DMODEL];  // L1 hit
            yb[(size_t)(l0 + r) * DMODEL] = fmaf(Dd, xv, sum);
        }
        __syncthreads();
    }
}

extern "C" void kernel_launch(void* const* d_in, const int* in_sizes, int n_in,
                              void* d_out, int out_size)
{
    const float* x      = (const float*)d_in[0];  // [8, 2048, 1024]
    const float* log_dt = (const float*)d_in[1];  // [1024]
    const float* Bm     = (const float*)d_in[2];  // [1024, 64]
    const float* Cm     = (const float*)d_in[3];  // [1024, 64]
    const float* Dv     = (const float*)d_in[4];  // [1024]
    float*       y      = (float*)d_out;          // [8, 2048, 1024]

    dim3 grid(DMODEL / CHT, BATCH);   // (32, 8) = 256 blocks
    dim3 block(WARPS * 32);           // 256 threads
    s4d_recurrence_kernel<<<grid, block>>>(x, log_dt, Bm, Cm, Dv, y);
}

// round 2
// speedup vs baseline: 1.2077x; 1.2077x over previous
#include <cuda_runtime.h>
#include <cuda_bf16.h>

// S4D forward as an exact diagonal-SSM recurrence:
//   a[d,n]  = exp(dt_d * A_n),  A_n = -0.5*(n+1)
//   cb[d,n] = C[d,n]*B[d,n]*expm1(dt_d*A_n)/A_n
//   h_n[l]  = a_n*h_n[l-1] + x[l],   y[l] = sum_n cb_n*h_n[l] + D_d*x[l]
//
// R2: packed fma.rn.f32x2 (2 states per 64-bit reg, PTX-only instruction),
//     double-buffered smem partials -> single __syncthreads per 16-step round.

#define BATCH   8
#define LEN     2048
#define DMODEL  1024
#define NSTATE  64

#define WARPS   8
#define SPT     8      // states per thread
#define PAIRS   4      // SPT/2 packed f32x2 lanes
#define CHT     32     // channel tile (lanes)
#define RST     16     // timesteps per reduction round

typedef unsigned long long u64;

__device__ __forceinline__ u64 pack2(float lo, float hi) {
    u64 r; asm("mov.b64 %0, {%1,%2};" : "=l"(r) : "f"(lo), "f"(hi)); return r;
}
__device__ __forceinline__ void unpack2(u64 v, float& lo, float& hi) {
    asm("mov.b64 {%0,%1}, %2;" : "=f"(lo), "=f"(hi) : "l"(v));
}
__device__ __forceinline__ u64 fma2(u64 a, u64 b, u64 c) {
    u64 d; asm("fma.rn.f32x2 %0, %1, %2, %3;" : "=l"(d) : "l"(a), "l"(b), "l"(c)); return d;
}
__device__ __forceinline__ u64 mul2(u64 a, u64 b) {
    u64 d; asm("mul.rn.f32x2 %0, %1, %2;" : "=l"(d) : "l"(a), "l"(b)); return d;
}
__device__ __forceinline__ u64 add2(u64 a, u64 b) {
    u64 d; asm("add.rn.f32x2 %0, %1, %2;" : "=l"(d) : "l"(a), "l"(b)); return d;
}

__global__ __launch_bounds__(WARPS * 32)
void s4d_recurrence_kernel(const float* __restrict__ x,
                           const float* __restrict__ log_dt,
                           const float* __restrict__ Bm,
                           const float* __restrict__ Cm,
                           const float* __restrict__ Dv,
                           float* __restrict__ y)
{
    __shared__ u64 P[2][WARPS][RST][CHT];   // packed float2 partials, 2 buffers

    const int lane = threadIdx.x & 31;
    const int w    = threadIdx.x >> 5;
    const int d    = blockIdx.x * CHT + lane;
    const int b    = blockIdx.y;

    // ---- per-thread discretized parameters (8 states, packed in pairs) ----
    u64 a2[PAIRS], cb2[PAIRS], s2[PAIRS];
    {
        const float dt = expf(log_dt[d]);
        #pragma unroll
        for (int i = 0; i < PAIRS; i++) {
            float av[2], cbv[2];
            #pragma unroll
            for (int h = 0; h < 2; h++) {
                const int   n   = w * SPT + 2 * i + h;
                const float An  = -0.5f * (float)(n + 1);
                const float dtA = dt * An;
                av[h]  = expf(dtA);
                cbv[h] = Cm[d * NSTATE + n] * Bm[d * NSTATE + n] * (expm1f(dtA) / An);
            }
            a2[i]  = pack2(av[0], av[1]);
            cb2[i] = pack2(cbv[0], cbv[1]);
            s2[i]  = 0ull;
        }
    }
    const float Dd = Dv[d];

    const float* xb = x + (size_t)b * LEN * DMODEL + d;
    float*       yb = y + (size_t)b * LEN * DMODEL + d;

    #pragma unroll 1
    for (int l0 = 0; l0 < LEN; l0 += 2 * RST) {
        #pragma unroll
        for (int buf = 0; buf < 2; buf++) {
            const int base = l0 + buf * RST;

            // ---- compute phase: 16 steps, packed FFMA2, partials -> smem ----
            #pragma unroll
            for (int r = 0; r < RST; r++) {
                const float xv = xb[(size_t)(base + r) * DMODEL];
                const u64   xx = pack2(xv, xv);
                #pragma unroll
                for (int i = 0; i < PAIRS; i++)
                    s2[i] = fma2(a2[i], s2[i], xx);
                u64 acc = mul2(cb2[0], s2[0]);
                #pragma unroll
                for (int i = 1; i < PAIRS; i++)
                    acc = fma2(cb2[i], s2[i], acc);
                P[buf][w][r][lane] = acc;
            }
            __syncthreads();

            // ---- cross-warp reduce: warp w handles rows r=w, w+8 ----
            #pragma unroll
            for (int k = 0; k < 2; k++) {
                const int r = w + k * WARPS;
                u64 sum = P[buf][0][r][lane];
                #pragma unroll
                for (int ww = 1; ww < WARPS; ww++)
                    sum = add2(sum, P[buf][ww][r][lane]);
                float lo, hi;
                unpack2(sum, lo, hi);
                const float xv = xb[(size_t)(base + r) * DMODEL];  // L1 hit
                yb[(size_t)(base + r) * DMODEL] = fmaf(Dd, xv, lo + hi);
            }
            // no second barrier: next round writes the OTHER buffer; this
            // buffer is next written only after the NEXT barrier, by which
            // time every warp has finished reading it.
        }
    }
}

extern "C" void kernel_launch(void* const* d_in, const int* in_sizes, int n_in,
                              void* d_out, int out_size)
{
    const float* x      = (const float*)d_in[0];  // [8, 2048, 1024]
    const float* log_dt = (const float*)d_in[1];  // [1024]
    const float* Bm     = (const float*)d_in[2];  // [1024, 64]
    const float* Cm     = (const float*)d_in[3];  // [1024, 64]
    const float* Dv     = (const float*)d_in[4];  // [1024]
    float*       y      = (float*)d_out;          // [8, 2048, 1024]

    dim3 grid(DMODEL / CHT, BATCH);   // (32, 8) = 256 blocks
    dim3 block(WARPS * 32);           // 256 threads
    s4d_recurrence_kernel<<<grid, block>>>(x, log_dt, Bm, Cm, Dv, y);
}